// round 6
// baseline (speedup 1.0000x reference)
#include <cuda_runtime.h>
#include <cstdint>

#define B_ 64
#define T_ 128
#define E_ 256
#define H_ 256          // HH
#define M_ (B_ * T_)    // 8192

// Scratch for x_proj of the current level (reused between levels)
__device__ float g_xp[M_ * H_];

// ---------------- helpers ----------------

__device__ __forceinline__ void fma2(unsigned long long &d,
                                     unsigned long long a,
                                     unsigned long long b) {
    asm("fma.rn.f32x2 %0, %1, %2, %0;" : "+l"(d) : "l"(a), "l"(b));
}

__device__ __forceinline__ unsigned long long pack2(float a, float b) {
    unsigned long long r;
    asm("mov.b64 %0, {%1, %2};" : "=l"(r) : "f"(a), "f"(b));
    return r;
}

__device__ __forceinline__ float lo32(unsigned long long v) {
    return __uint_as_float((unsigned)(v & 0xffffffffull));
}
__device__ __forceinline__ float hi32(unsigned long long v) {
    return __uint_as_float((unsigned)(v >> 32));
}

__device__ __forceinline__ float fast_tanh(float x) {
    float e = __expf(2.0f * x);
    return 1.0f - __fdividef(2.0f, e + 1.0f);
}

// ---------------- x_proj GEMM ----------------
__global__ __launch_bounds__(256) void xp_gemm(
    const float* __restrict__ Asrc, long lda, const int* __restrict__ tokens,
    const float* __restrict__ Bw, const float* __restrict__ bias)
{
    __shared__ float As[8][128];
    __shared__ float Bs[8][128];

    const int m0 = blockIdx.x * 128;
    const int n0 = blockIdx.y * 128;
    const int tid = threadIdx.x;
    const int tx = tid & 15;
    const int ty = tid >> 4;
    const int lrow = tid >> 1;
    const int lc4 = (tid & 1) * 4;

    unsigned long long acc[8][4];
#pragma unroll
    for (int i = 0; i < 8; i++)
#pragma unroll
        for (int j = 0; j < 4; j++) acc[i][j] = 0ull;

    const float* aptr;
    {
        long ar = m0 + lrow;
        if (tokens) aptr = Asrc + (long)__ldg(tokens + ar) * lda;
        else        aptr = Asrc + ar * lda;
    }
    const float* bptr = Bw + (long)(n0 + lrow) * 256;

    for (int c = 0; c < 256; c += 8) {
        float4 av = *reinterpret_cast<const float4*>(aptr + c + lc4);
        float4 bv = *reinterpret_cast<const float4*>(bptr + c + lc4);
        __syncthreads();
        As[lc4 + 0][lrow] = av.x; As[lc4 + 1][lrow] = av.y;
        As[lc4 + 2][lrow] = av.z; As[lc4 + 3][lrow] = av.w;
        Bs[lc4 + 0][lrow] = bv.x; Bs[lc4 + 1][lrow] = bv.y;
        Bs[lc4 + 2][lrow] = bv.z; Bs[lc4 + 3][lrow] = bv.w;
        __syncthreads();
#pragma unroll
        for (int k = 0; k < 8; k++) {
            float a[8];
            *reinterpret_cast<float4*>(&a[0]) =
                *reinterpret_cast<const float4*>(&As[k][ty * 8]);
            *reinterpret_cast<float4*>(&a[4]) =
                *reinterpret_cast<const float4*>(&As[k][ty * 8 + 4]);
            const ulonglong2* bb =
                reinterpret_cast<const ulonglong2*>(&Bs[k][tx * 8]);
            ulonglong2 b01 = bb[0], b23 = bb[1];
            unsigned long long b2[4] = {b01.x, b01.y, b23.x, b23.y};
#pragma unroll
            for (int i = 0; i < 8; i++) {
                unsigned long long a2 = pack2(a[i], a[i]);
                fma2(acc[i][0], a2, b2[0]);
                fma2(acc[i][1], a2, b2[1]);
                fma2(acc[i][2], a2, b2[2]);
                fma2(acc[i][3], a2, b2[3]);
            }
        }
    }

#pragma unroll
    for (int i = 0; i < 8; i++) {
        int m = m0 + ty * 8 + i;
        float* crow = g_xp + (long)m * 256 + n0 + tx * 8;
#pragma unroll
        for (int j = 0; j < 4; j++) {
            float2 v;
            v.x = lo32(acc[i][j]) + __ldg(bias + n0 + tx * 8 + 2 * j);
            v.y = hi32(acc[i][j]) + __ldg(bias + n0 + tx * 8 + 2 * j + 1);
            *reinterpret_cast<float2*>(crow + 2 * j) = v;
        }
    }
}

// ---------------- LTC scan (single CTA per batch, 2 rows/thread) ----------------
// Thread tid computes the (tid&1)-th 128-col half of rows (tid&~1, tid|1).
// One shfl.xor(1) combines the halves; each thread finalizes row `tid`.
// Row tid&~1 weights (64 ull) + half of row tid|1 (32 ull) in registers;
// remaining 32 ull of row tid|1 streamed from smem with double-buffered
// chunk prefetch (8-ull chunks, loaded one phase ahead of use).
// hbuf halves at 132-float skew -> even/odd lane LDS.128 conflict-free.
#define HROW 264                                  // 2 halves * 132 floats
#define SMEM_SCAN (32 * 256 * 8 + 2 * HROW * 4)

__global__ void __launch_bounds__(256, 1) ltc_scan(
    const float* __restrict__ W_rec,
    const float* __restrict__ mask,
    const float* __restrict__ tau_raw,
    float* __restrict__ out, int col_off)
{
    extern __shared__ __align__(16) char smem_raw[];
    unsigned long long* ws = reinterpret_cast<unsigned long long*>(smem_raw);
    float* hbuf = reinterpret_cast<float*>(smem_raw + 32 * 256 * 8); // [2][HROW]

    const int b = blockIdx.x;
    const int tid = threadIdx.x;
    const int ch = tid & 1;            // column half
    const int r0 = tid & ~1;           // even row of the pair
    const int r1 = r0 | 1;             // odd row

    // ---- weights ----
    unsigned long long w0[64], w1[32];
    {
        const float2* wr0 = reinterpret_cast<const float2*>(W_rec + (long)r0 * 256) + 64 * ch;
        const float2* mk0 = reinterpret_cast<const float2*>(mask + (long)r0 * 256) + 64 * ch;
#pragma unroll
        for (int j = 0; j < 64; j++) {
            float2 a = __ldg(wr0 + j), m = __ldg(mk0 + j);
            w0[j] = pack2(a.x * m.x, a.y * m.y);
        }
        const float2* wr1 = reinterpret_cast<const float2*>(W_rec + (long)r1 * 256) + 64 * ch;
        const float2* mk1 = reinterpret_cast<const float2*>(mask + (long)r1 * 256) + 64 * ch;
#pragma unroll
        for (int j = 0; j < 32; j++) {
            float2 a = __ldg(wr1 + j), m = __ldg(mk1 + j);
            w1[j] = pack2(a.x * m.x, a.y * m.y);
        }
        // streamed: last 32 ull of row r1's col-half, own smem slot
#pragma unroll
        for (int k = 0; k < 32; k++) {
            float2 a = __ldg(wr1 + 32 + k), m = __ldg(mk1 + 32 + k);
            ws[k * 256 + tid] = pack2(a.x * m.x, a.y * m.y);
        }
    }

    float inv_tau;
    {
        float tr = __ldg(tau_raw + tid);
        float tau = log1pf(expf(tr)) + 0.1f;   // softplus + 0.1
        inv_tau = 1.0f / tau;
    }
    float hreg = 0.0f;

    for (int i = tid; i < 2 * HROW; i += 256) hbuf[i] = 0.0f;
    __syncthreads();

    const float* xpp = g_xp + ((long)b * T_) * H_ + tid;
    float* outp = out + ((long)b * T_) * 512 + col_off + tid;
    float xq = __ldg(xpp);                       // xp for t=0
    const int mypos = (tid < 128) ? tid : (tid + 4);   // skewed store slot

    const unsigned long long* wsp = ws + tid;
    unsigned long long wa[8], wb[8];

    for (int t = 0; t < T_; ++t) {
        const int cur = t & 1;
        const ulonglong2* hq =
            reinterpret_cast<const ulonglong2*>(hbuf + cur * HROW + ch * 132);

        // preload streamed chunks 0,1 (used at phases 4,5)
#pragma unroll
        for (int i = 0; i < 8; i++) wa[i] = wsp[i * 256];
#pragma unroll
        for (int i = 0; i < 8; i++) wb[i] = wsp[(8 + i) * 256];

        // prefetch next step's xp under the matvec
        float xn = 0.0f;
        if (t + 1 < T_) xn = __ldg(xpp + (long)(t + 1) * H_);

        unsigned long long A0 = 0ull, A1 = 0ull, B0 = 0ull, B1 = 0ull;
#pragma unroll
        for (int ph = 0; ph < 8; ph++) {
            ulonglong2 x0 = hq[4 * ph + 0], x1 = hq[4 * ph + 1];
            ulonglong2 x2 = hq[4 * ph + 2], x3 = hq[4 * ph + 3];
            // row r0: fully register-resident
            fma2(A0, w0[8 * ph + 0], x0.x); fma2(A1, w0[8 * ph + 1], x0.y);
            fma2(A0, w0[8 * ph + 2], x1.x); fma2(A1, w0[8 * ph + 3], x1.y);
            fma2(A0, w0[8 * ph + 4], x2.x); fma2(A1, w0[8 * ph + 5], x2.y);
            fma2(A0, w0[8 * ph + 6], x3.x); fma2(A1, w0[8 * ph + 7], x3.y);
            if (ph < 4) {
                // row r1, register part
                fma2(B0, w1[8 * ph + 0], x0.x); fma2(B1, w1[8 * ph + 1], x0.y);
                fma2(B0, w1[8 * ph + 2], x1.x); fma2(B1, w1[8 * ph + 3], x1.y);
                fma2(B0, w1[8 * ph + 4], x2.x); fma2(B1, w1[8 * ph + 5], x2.y);
                fma2(B0, w1[8 * ph + 6], x3.x); fma2(B1, w1[8 * ph + 7], x3.y);
            } else {
                // row r1, streamed part (chunk loaded >=1 phase earlier)
                unsigned long long* wc = (ph & 1) ? wb : wa;
                fma2(B0, wc[0], x0.x); fma2(B1, wc[1], x0.y);
                fma2(B0, wc[2], x1.x); fma2(B1, wc[3], x1.y);
                fma2(B0, wc[4], x2.x); fma2(B1, wc[5], x2.y);
                fma2(B0, wc[6], x3.x); fma2(B1, wc[7], x3.y);
                if (ph < 6) {   // prefetch chunk ph-2 (k base (ph-2)*8) for ph+2
#pragma unroll
                    for (int i = 0; i < 8; i++)
                        wc[i] = wsp[((ph - 2) * 8 + i) * 256];
                }
            }
        }

        float s0 = (lo32(A0) + hi32(A0)) + (lo32(A1) + hi32(A1));
        float s1 = (lo32(B0) + hi32(B0)) + (lo32(B1) + hi32(B1));
        s0 += __shfl_xor_sync(0xffffffffu, s0, 1);
        s1 += __shfl_xor_sync(0xffffffffu, s1, 1);
        float s = ch ? s1 : s0;                // my row's full dot product

        float pre = s + xq;
        float hn = fmaf(fast_tanh(pre) - hreg, inv_tau, hreg);
        hreg = hn;
        outp[(long)t * 512] = hn;
        hbuf[(cur ^ 1) * HROW + mypos] = hn;   // publish for next step
        xq = xn;
        __syncthreads();
    }
}

// ---------------- launcher ----------------

extern "C" void kernel_launch(void* const* d_in, const int* in_sizes, int n_in,
                              void* d_out, int out_size) {
    const int*   tokens = (const int*)  d_in[0];
    const float* emb    = (const float*)d_in[1];
    const float* W_in0  = (const float*)d_in[2];
    const float* W_rec0 = (const float*)d_in[3];
    const float* b0     = (const float*)d_in[4];
    const float* tau0   = (const float*)d_in[5];
    const float* mask0  = (const float*)d_in[6];
    const float* W_in1  = (const float*)d_in[7];
    const float* W_rec1 = (const float*)d_in[8];
    const float* b1     = (const float*)d_in[9];
    const float* tau1   = (const float*)d_in[10];
    const float* mask1  = (const float*)d_in[11];
    float* out = (float*)d_out;

    cudaFuncSetAttribute(ltc_scan,
                         cudaFuncAttributeMaxDynamicSharedMemorySize,
                         SMEM_SCAN);

    dim3 gemm_grid(M_ / 128, 2);

    // level 0
    xp_gemm<<<gemm_grid, 256>>>(emb, E_, tokens, W_in0, b0);
    ltc_scan<<<B_, 256, SMEM_SCAN>>>(W_rec0, mask0, tau0, out, 0);

    // level 1
    xp_gemm<<<gemm_grid, 256>>>(out, 512, nullptr, W_in1, b1);
    ltc_scan<<<B_, 256, SMEM_SCAN>>>(W_rec1, mask1, tau1, out, 256);
}

// round 7
// speedup vs baseline: 1.0023x; 1.0023x over previous
#include <cuda_runtime.h>
#include <cstdint>

#define B_ 64
#define T_ 128
#define E_ 256
#define H_ 256          // HH
#define M_ (B_ * T_)    // 8192

// Scratch for x_proj of the current level (reused between levels)
__device__ float g_xp[M_ * H_];

// ---------------- helpers ----------------

__device__ __forceinline__ void fma2(unsigned long long &d,
                                     unsigned long long a,
                                     unsigned long long b) {
    asm("fma.rn.f32x2 %0, %1, %2, %0;" : "+l"(d) : "l"(a), "l"(b));
}

__device__ __forceinline__ unsigned long long pack2(float a, float b) {
    unsigned long long r;
    asm("mov.b64 %0, {%1, %2};" : "=l"(r) : "f"(a), "f"(b));
    return r;
}

__device__ __forceinline__ float lo32(unsigned long long v) {
    return __uint_as_float((unsigned)(v & 0xffffffffull));
}
__device__ __forceinline__ float hi32(unsigned long long v) {
    return __uint_as_float((unsigned)(v >> 32));
}

__device__ __forceinline__ float fast_tanh(float x) {
    float e = __expf(2.0f * x);
    return 1.0f - __fdividef(2.0f, e + 1.0f);
}

// ---------------- x_proj GEMM ----------------
__global__ __launch_bounds__(256) void xp_gemm(
    const float* __restrict__ Asrc, long lda, const int* __restrict__ tokens,
    const float* __restrict__ Bw, const float* __restrict__ bias)
{
    __shared__ float As[8][128];
    __shared__ float Bs[8][128];

    const int m0 = blockIdx.x * 128;
    const int n0 = blockIdx.y * 128;
    const int tid = threadIdx.x;
    const int tx = tid & 15;
    const int ty = tid >> 4;
    const int lrow = tid >> 1;
    const int lc4 = (tid & 1) * 4;

    unsigned long long acc[8][4];
#pragma unroll
    for (int i = 0; i < 8; i++)
#pragma unroll
        for (int j = 0; j < 4; j++) acc[i][j] = 0ull;

    const float* aptr;
    {
        long ar = m0 + lrow;
        if (tokens) aptr = Asrc + (long)__ldg(tokens + ar) * lda;
        else        aptr = Asrc + ar * lda;
    }
    const float* bptr = Bw + (long)(n0 + lrow) * 256;

    for (int c = 0; c < 256; c += 8) {
        float4 av = *reinterpret_cast<const float4*>(aptr + c + lc4);
        float4 bv = *reinterpret_cast<const float4*>(bptr + c + lc4);
        __syncthreads();
        As[lc4 + 0][lrow] = av.x; As[lc4 + 1][lrow] = av.y;
        As[lc4 + 2][lrow] = av.z; As[lc4 + 3][lrow] = av.w;
        Bs[lc4 + 0][lrow] = bv.x; Bs[lc4 + 1][lrow] = bv.y;
        Bs[lc4 + 2][lrow] = bv.z; Bs[lc4 + 3][lrow] = bv.w;
        __syncthreads();
#pragma unroll
        for (int k = 0; k < 8; k++) {
            float a[8];
            *reinterpret_cast<float4*>(&a[0]) =
                *reinterpret_cast<const float4*>(&As[k][ty * 8]);
            *reinterpret_cast<float4*>(&a[4]) =
                *reinterpret_cast<const float4*>(&As[k][ty * 8 + 4]);
            const ulonglong2* bb =
                reinterpret_cast<const ulonglong2*>(&Bs[k][tx * 8]);
            ulonglong2 b01 = bb[0], b23 = bb[1];
            unsigned long long b2[4] = {b01.x, b01.y, b23.x, b23.y};
#pragma unroll
            for (int i = 0; i < 8; i++) {
                unsigned long long a2 = pack2(a[i], a[i]);
                fma2(acc[i][0], a2, b2[0]);
                fma2(acc[i][1], a2, b2[1]);
                fma2(acc[i][2], a2, b2[2]);
                fma2(acc[i][3], a2, b2[3]);
            }
        }
    }

#pragma unroll
    for (int i = 0; i < 8; i++) {
        int m = m0 + ty * 8 + i;
        float* crow = g_xp + (long)m * 256 + n0 + tx * 8;
#pragma unroll
        for (int j = 0; j < 4; j++) {
            float2 v;
            v.x = lo32(acc[i][j]) + __ldg(bias + n0 + tx * 8 + 2 * j);
            v.y = hi32(acc[i][j]) + __ldg(bias + n0 + tx * 8 + 2 * j + 1);
            *reinterpret_cast<float2*>(crow + 2 * j) = v;
        }
    }
}

// ---------------- LTC scan (single CTA per batch, 2 rows/thread) ----------------
// Thread tid computes the (tid&1)-th 128-col half of rows (tid&~1, tid|1).
// One shfl.xor(1) combines the halves; each thread finalizes row `tid`.
// Row tid&~1 weights (64 ull) + half of row tid|1 (32 ull) in registers;
// remaining 32 ull of row tid|1 streamed from smem with double-buffered
// chunk prefetch (8-ull chunks, loaded one phase ahead of use).
// hbuf halves at 132-float skew -> even/odd lane LDS.128 conflict-free.
#define HROW 264                                  // 2 halves * 132 floats
#define SMEM_SCAN (32 * 256 * 8 + 2 * HROW * 4)

__global__ void __launch_bounds__(256, 1) ltc_scan(
    const float* __restrict__ W_rec,
    const float* __restrict__ mask,
    const float* __restrict__ tau_raw,
    float* __restrict__ out, int col_off)
{
    extern __shared__ __align__(16) char smem_raw[];
    unsigned long long* ws = reinterpret_cast<unsigned long long*>(smem_raw);
    float* hbuf = reinterpret_cast<float*>(smem_raw + 32 * 256 * 8); // [2][HROW]

    const int b = blockIdx.x;
    const int tid = threadIdx.x;
    const int ch = tid & 1;            // column half
    const int r0 = tid & ~1;           // even row of the pair
    const int r1 = r0 | 1;             // odd row

    // ---- weights ----
    unsigned long long w0[64], w1[32];
    {
        const float2* wr0 = reinterpret_cast<const float2*>(W_rec + (long)r0 * 256) + 64 * ch;
        const float2* mk0 = reinterpret_cast<const float2*>(mask + (long)r0 * 256) + 64 * ch;
#pragma unroll
        for (int j = 0; j < 64; j++) {
            float2 a = __ldg(wr0 + j), m = __ldg(mk0 + j);
            w0[j] = pack2(a.x * m.x, a.y * m.y);
        }
        const float2* wr1 = reinterpret_cast<const float2*>(W_rec + (long)r1 * 256) + 64 * ch;
        const float2* mk1 = reinterpret_cast<const float2*>(mask + (long)r1 * 256) + 64 * ch;
#pragma unroll
        for (int j = 0; j < 32; j++) {
            float2 a = __ldg(wr1 + j), m = __ldg(mk1 + j);
            w1[j] = pack2(a.x * m.x, a.y * m.y);
        }
        // streamed: last 32 ull of row r1's col-half, own smem slot
#pragma unroll
        for (int k = 0; k < 32; k++) {
            float2 a = __ldg(wr1 + 32 + k), m = __ldg(mk1 + 32 + k);
            ws[k * 256 + tid] = pack2(a.x * m.x, a.y * m.y);
        }
    }

    float inv_tau;
    {
        float tr = __ldg(tau_raw + tid);
        float tau = log1pf(expf(tr)) + 0.1f;   // softplus + 0.1
        inv_tau = 1.0f / tau;
    }
    float hreg = 0.0f;

    for (int i = tid; i < 2 * HROW; i += 256) hbuf[i] = 0.0f;
    __syncthreads();

    const float* xpp = g_xp + ((long)b * T_) * H_ + tid;
    float* outp = out + ((long)b * T_) * 512 + col_off + tid;
    float xq = __ldg(xpp);                       // xp for t=0
    const int mypos = (tid < 128) ? tid : (tid + 4);   // skewed store slot

    const unsigned long long* wsp = ws + tid;
    unsigned long long wa[8], wb[8];

    for (int t = 0; t < T_; ++t) {
        const int cur = t & 1;
        const ulonglong2* hq =
            reinterpret_cast<const ulonglong2*>(hbuf + cur * HROW + ch * 132);

        // preload streamed chunks 0,1 (used at phases 4,5)
#pragma unroll
        for (int i = 0; i < 8; i++) wa[i] = wsp[i * 256];
#pragma unroll
        for (int i = 0; i < 8; i++) wb[i] = wsp[(8 + i) * 256];

        // prefetch next step's xp under the matvec
        float xn = 0.0f;
        if (t + 1 < T_) xn = __ldg(xpp + (long)(t + 1) * H_);

        unsigned long long A0 = 0ull, A1 = 0ull, B0 = 0ull, B1 = 0ull;
#pragma unroll
        for (int ph = 0; ph < 8; ph++) {
            ulonglong2 x0 = hq[4 * ph + 0], x1 = hq[4 * ph + 1];
            ulonglong2 x2 = hq[4 * ph + 2], x3 = hq[4 * ph + 3];
            // row r0: fully register-resident
            fma2(A0, w0[8 * ph + 0], x0.x); fma2(A1, w0[8 * ph + 1], x0.y);
            fma2(A0, w0[8 * ph + 2], x1.x); fma2(A1, w0[8 * ph + 3], x1.y);
            fma2(A0, w0[8 * ph + 4], x2.x); fma2(A1, w0[8 * ph + 5], x2.y);
            fma2(A0, w0[8 * ph + 6], x3.x); fma2(A1, w0[8 * ph + 7], x3.y);
            if (ph < 4) {
                // row r1, register part
                fma2(B0, w1[8 * ph + 0], x0.x); fma2(B1, w1[8 * ph + 1], x0.y);
                fma2(B0, w1[8 * ph + 2], x1.x); fma2(B1, w1[8 * ph + 3], x1.y);
                fma2(B0, w1[8 * ph + 4], x2.x); fma2(B1, w1[8 * ph + 5], x2.y);
                fma2(B0, w1[8 * ph + 6], x3.x); fma2(B1, w1[8 * ph + 7], x3.y);
            } else {
                // row r1, streamed part (chunk loaded >=1 phase earlier)
                unsigned long long* wc = (ph & 1) ? wb : wa;
                fma2(B0, wc[0], x0.x); fma2(B1, wc[1], x0.y);
                fma2(B0, wc[2], x1.x); fma2(B1, wc[3], x1.y);
                fma2(B0, wc[4], x2.x); fma2(B1, wc[5], x2.y);
                fma2(B0, wc[6], x3.x); fma2(B1, wc[7], x3.y);
                if (ph < 6) {   // prefetch chunk ph-2 (k base (ph-2)*8) for ph+2
#pragma unroll
                    for (int i = 0; i < 8; i++)
                        wc[i] = wsp[((ph - 2) * 8 + i) * 256];
                }
            }
        }

        float s0 = (lo32(A0) + hi32(A0)) + (lo32(A1) + hi32(A1));
        float s1 = (lo32(B0) + hi32(B0)) + (lo32(B1) + hi32(B1));
        s0 += __shfl_xor_sync(0xffffffffu, s0, 1);
        s1 += __shfl_xor_sync(0xffffffffu, s1, 1);
        float s = ch ? s1 : s0;                // my row's full dot product

        float pre = s + xq;
        float hn = fmaf(fast_tanh(pre) - hreg, inv_tau, hreg);
        hreg = hn;
        outp[(long)t * 512] = hn;
        hbuf[(cur ^ 1) * HROW + mypos] = hn;   // publish for next step
        xq = xn;
        __syncthreads();
    }
}

// ---------------- launcher ----------------

extern "C" void kernel_launch(void* const* d_in, const int* in_sizes, int n_in,
                              void* d_out, int out_size) {
    const int*   tokens = (const int*)  d_in[0];
    const float* emb    = (const float*)d_in[1];
    const float* W_in0  = (const float*)d_in[2];
    const float* W_rec0 = (const float*)d_in[3];
    const float* b0     = (const float*)d_in[4];
    const float* tau0   = (const float*)d_in[5];
    const float* mask0  = (const float*)d_in[6];
    const float* W_in1  = (const float*)d_in[7];
    const float* W_rec1 = (const float*)d_in[8];
    const float* b1     = (const float*)d_in[9];
    const float* tau1   = (const float*)d_in[10];
    const float* mask1  = (const float*)d_in[11];
    float* out = (float*)d_out;

    cudaFuncSetAttribute(ltc_scan,
                         cudaFuncAttributeMaxDynamicSharedMemorySize,
                         SMEM_SCAN);

    dim3 gemm_grid(M_ / 128, 2);

    // level 0
    xp_gemm<<<gemm_grid, 256>>>(emb, E_, tokens, W_in0, b0);
    ltc_scan<<<B_, 256, SMEM_SCAN>>>(W_rec0, mask0, tau0, out, 0);

    // level 1
    xp_gemm<<<gemm_grid, 256>>>(out, 512, nullptr, W_in1, b1);
    ltc_scan<<<B_, 256, SMEM_SCAN>>>(W_rec1, mask1, tau1, out, 256);
}

// round 8
// speedup vs baseline: 1.0069x; 1.0046x over previous
#include <cuda_runtime.h>
#include <cstdint>

#define B_ 64
#define T_ 128
#define E_ 256
#define H_ 256          // HH
#define M_ (B_ * T_)    // 8192

// Scratch for x_proj of the current level (reused between levels)
__device__ float g_xp[M_ * H_];

// ---------------- helpers ----------------

__device__ __forceinline__ void fma2(unsigned long long &d,
                                     unsigned long long a,
                                     unsigned long long b) {
    asm("fma.rn.f32x2 %0, %1, %2, %0;" : "+l"(d) : "l"(a), "l"(b));
}

__device__ __forceinline__ unsigned long long pack2(float a, float b) {
    unsigned long long r;
    asm("mov.b64 %0, {%1, %2};" : "=l"(r) : "f"(a), "f"(b));
    return r;
}

__device__ __forceinline__ float lo32(unsigned long long v) {
    return __uint_as_float((unsigned)(v & 0xffffffffull));
}
__device__ __forceinline__ float hi32(unsigned long long v) {
    return __uint_as_float((unsigned)(v >> 32));
}

__device__ __forceinline__ float fast_tanh(float x) {
    float e = __expf(2.0f * x);
    return 1.0f - __fdividef(2.0f, e + 1.0f);
}

// ---------------- x_proj GEMM ----------------
__global__ __launch_bounds__(256) void xp_gemm(
    const float* __restrict__ Asrc, long lda, const int* __restrict__ tokens,
    const float* __restrict__ Bw, const float* __restrict__ bias)
{
    __shared__ float As[8][128];
    __shared__ float Bs[8][128];

    const int m0 = blockIdx.x * 128;
    const int n0 = blockIdx.y * 128;
    const int tid = threadIdx.x;
    const int tx = tid & 15;
    const int ty = tid >> 4;
    const int lrow = tid >> 1;
    const int lc4 = (tid & 1) * 4;

    unsigned long long acc[8][4];
#pragma unroll
    for (int i = 0; i < 8; i++)
#pragma unroll
        for (int j = 0; j < 4; j++) acc[i][j] = 0ull;

    const float* aptr;
    {
        long ar = m0 + lrow;
        if (tokens) aptr = Asrc + (long)__ldg(tokens + ar) * lda;
        else        aptr = Asrc + ar * lda;
    }
    const float* bptr = Bw + (long)(n0 + lrow) * 256;

    for (int c = 0; c < 256; c += 8) {
        float4 av = *reinterpret_cast<const float4*>(aptr + c + lc4);
        float4 bv = *reinterpret_cast<const float4*>(bptr + c + lc4);
        __syncthreads();
        As[lc4 + 0][lrow] = av.x; As[lc4 + 1][lrow] = av.y;
        As[lc4 + 2][lrow] = av.z; As[lc4 + 3][lrow] = av.w;
        Bs[lc4 + 0][lrow] = bv.x; Bs[lc4 + 1][lrow] = bv.y;
        Bs[lc4 + 2][lrow] = bv.z; Bs[lc4 + 3][lrow] = bv.w;
        __syncthreads();
#pragma unroll
        for (int k = 0; k < 8; k++) {
            float a[8];
            *reinterpret_cast<float4*>(&a[0]) =
                *reinterpret_cast<const float4*>(&As[k][ty * 8]);
            *reinterpret_cast<float4*>(&a[4]) =
                *reinterpret_cast<const float4*>(&As[k][ty * 8 + 4]);
            const ulonglong2* bb =
                reinterpret_cast<const ulonglong2*>(&Bs[k][tx * 8]);
            ulonglong2 b01 = bb[0], b23 = bb[1];
            unsigned long long b2[4] = {b01.x, b01.y, b23.x, b23.y};
#pragma unroll
            for (int i = 0; i < 8; i++) {
                unsigned long long a2 = pack2(a[i], a[i]);
                fma2(acc[i][0], a2, b2[0]);
                fma2(acc[i][1], a2, b2[1]);
                fma2(acc[i][2], a2, b2[2]);
                fma2(acc[i][3], a2, b2[3]);
            }
        }
    }

#pragma unroll
    for (int i = 0; i < 8; i++) {
        int m = m0 + ty * 8 + i;
        float* crow = g_xp + (long)m * 256 + n0 + tx * 8;
#pragma unroll
        for (int j = 0; j < 4; j++) {
            float2 v;
            v.x = lo32(acc[i][j]) + __ldg(bias + n0 + tx * 8 + 2 * j);
            v.y = hi32(acc[i][j]) + __ldg(bias + n0 + tx * 8 + 2 * j + 1);
            *reinterpret_cast<float2*>(crow + 2 * j) = v;
        }
    }
}

// ---------------- LTC scan (single CTA per batch, 2 rows/thread) ----------------
// Thread tid computes the (tid&1)-th 128-col half of rows (tid&~1, tid|1).
// One shfl.xor(1) combines the halves; each thread finalizes row `tid`.
// Row tid&~1 weights (64 ull) + half of row tid|1 (32 ull) in registers;
// remaining 32 ull of row tid|1 streamed from smem with double-buffered
// chunk prefetch (8-ull chunks, loaded one phase ahead of use).
// hbuf halves at 132-float skew -> even/odd lane LDS.128 conflict-free.
#define HROW 264                                  // 2 halves * 132 floats
#define SMEM_SCAN (32 * 256 * 8 + 2 * HROW * 4)

__global__ void __launch_bounds__(256, 1) ltc_scan(
    const float* __restrict__ W_rec,
    const float* __restrict__ mask,
    const float* __restrict__ tau_raw,
    float* __restrict__ out, int col_off)
{
    extern __shared__ __align__(16) char smem_raw[];
    unsigned long long* ws = reinterpret_cast<unsigned long long*>(smem_raw);
    float* hbuf = reinterpret_cast<float*>(smem_raw + 32 * 256 * 8); // [2][HROW]

    const int b = blockIdx.x;
    const int tid = threadIdx.x;
    const int ch = tid & 1;            // column half
    const int r0 = tid & ~1;           // even row of the pair
    const int r1 = r0 | 1;             // odd row

    // ---- weights ----
    unsigned long long w0[64], w1[32];
    {
        const float2* wr0 = reinterpret_cast<const float2*>(W_rec + (long)r0 * 256) + 64 * ch;
        const float2* mk0 = reinterpret_cast<const float2*>(mask + (long)r0 * 256) + 64 * ch;
#pragma unroll
        for (int j = 0; j < 64; j++) {
            float2 a = __ldg(wr0 + j), m = __ldg(mk0 + j);
            w0[j] = pack2(a.x * m.x, a.y * m.y);
        }
        const float2* wr1 = reinterpret_cast<const float2*>(W_rec + (long)r1 * 256) + 64 * ch;
        const float2* mk1 = reinterpret_cast<const float2*>(mask + (long)r1 * 256) + 64 * ch;
#pragma unroll
        for (int j = 0; j < 32; j++) {
            float2 a = __ldg(wr1 + j), m = __ldg(mk1 + j);
            w1[j] = pack2(a.x * m.x, a.y * m.y);
        }
        // streamed: last 32 ull of row r1's col-half, own smem slot
#pragma unroll
        for (int k = 0; k < 32; k++) {
            float2 a = __ldg(wr1 + 32 + k), m = __ldg(mk1 + 32 + k);
            ws[k * 256 + tid] = pack2(a.x * m.x, a.y * m.y);
        }
    }

    float inv_tau;
    {
        float tr = __ldg(tau_raw + tid);
        float tau = log1pf(expf(tr)) + 0.1f;   // softplus + 0.1
        inv_tau = 1.0f / tau;
    }
    float hreg = 0.0f;

    for (int i = tid; i < 2 * HROW; i += 256) hbuf[i] = 0.0f;
    __syncthreads();

    const float* xpp = g_xp + ((long)b * T_) * H_ + tid;
    float* outp = out + ((long)b * T_) * 512 + col_off + tid;
    float xq = __ldg(xpp);                       // xp for t=0
    const int mypos = (tid < 128) ? tid : (tid + 4);   // skewed store slot

    const unsigned long long* wsp = ws + tid;
    unsigned long long wa[8], wb[8];

    for (int t = 0; t < T_; ++t) {
        const int cur = t & 1;
        const ulonglong2* hq =
            reinterpret_cast<const ulonglong2*>(hbuf + cur * HROW + ch * 132);

        // preload streamed chunks 0,1 (used at phases 4,5)
#pragma unroll
        for (int i = 0; i < 8; i++) wa[i] = wsp[i * 256];
#pragma unroll
        for (int i = 0; i < 8; i++) wb[i] = wsp[(8 + i) * 256];

        // prefetch next step's xp under the matvec
        float xn = 0.0f;
        if (t + 1 < T_) xn = __ldg(xpp + (long)(t + 1) * H_);

        unsigned long long A0 = 0ull, A1 = 0ull, B0 = 0ull, B1 = 0ull;
#pragma unroll
        for (int ph = 0; ph < 8; ph++) {
            ulonglong2 x0 = hq[4 * ph + 0], x1 = hq[4 * ph + 1];
            ulonglong2 x2 = hq[4 * ph + 2], x3 = hq[4 * ph + 3];
            // row r0: fully register-resident
            fma2(A0, w0[8 * ph + 0], x0.x); fma2(A1, w0[8 * ph + 1], x0.y);
            fma2(A0, w0[8 * ph + 2], x1.x); fma2(A1, w0[8 * ph + 3], x1.y);
            fma2(A0, w0[8 * ph + 4], x2.x); fma2(A1, w0[8 * ph + 5], x2.y);
            fma2(A0, w0[8 * ph + 6], x3.x); fma2(A1, w0[8 * ph + 7], x3.y);
            if (ph < 4) {
                // row r1, register part
                fma2(B0, w1[8 * ph + 0], x0.x); fma2(B1, w1[8 * ph + 1], x0.y);
                fma2(B0, w1[8 * ph + 2], x1.x); fma2(B1, w1[8 * ph + 3], x1.y);
                fma2(B0, w1[8 * ph + 4], x2.x); fma2(B1, w1[8 * ph + 5], x2.y);
                fma2(B0, w1[8 * ph + 6], x3.x); fma2(B1, w1[8 * ph + 7], x3.y);
            } else {
                // row r1, streamed part (chunk loaded >=1 phase earlier)
                unsigned long long* wc = (ph & 1) ? wb : wa;
                fma2(B0, wc[0], x0.x); fma2(B1, wc[1], x0.y);
                fma2(B0, wc[2], x1.x); fma2(B1, wc[3], x1.y);
                fma2(B0, wc[4], x2.x); fma2(B1, wc[5], x2.y);
                fma2(B0, wc[6], x3.x); fma2(B1, wc[7], x3.y);
                if (ph < 6) {   // prefetch chunk ph-2 (k base (ph-2)*8) for ph+2
#pragma unroll
                    for (int i = 0; i < 8; i++)
                        wc[i] = wsp[((ph - 2) * 8 + i) * 256];
                }
            }
        }

        float s0 = (lo32(A0) + hi32(A0)) + (lo32(A1) + hi32(A1));
        float s1 = (lo32(B0) + hi32(B0)) + (lo32(B1) + hi32(B1));
        s0 += __shfl_xor_sync(0xffffffffu, s0, 1);
        s1 += __shfl_xor_sync(0xffffffffu, s1, 1);
        float s = ch ? s1 : s0;                // my row's full dot product

        float pre = s + xq;
        float hn = fmaf(fast_tanh(pre) - hreg, inv_tau, hreg);
        hreg = hn;
        outp[(long)t * 512] = hn;
        hbuf[(cur ^ 1) * HROW + mypos] = hn;   // publish for next step
        xq = xn;
        __syncthreads();
    }
}

// ---------------- launcher ----------------

extern "C" void kernel_launch(void* const* d_in, const int* in_sizes, int n_in,
                              void* d_out, int out_size) {
    const int*   tokens = (const int*)  d_in[0];
    const float* emb    = (const float*)d_in[1];
    const float* W_in0  = (const float*)d_in[2];
    const float* W_rec0 = (const float*)d_in[3];
    const float* b0     = (const float*)d_in[4];
    const float* tau0   = (const float*)d_in[5];
    const float* mask0  = (const float*)d_in[6];
    const float* W_in1  = (const float*)d_in[7];
    const float* W_rec1 = (const float*)d_in[8];
    const float* b1     = (const float*)d_in[9];
    const float* tau1   = (const float*)d_in[10];
    const float* mask1  = (const float*)d_in[11];
    float* out = (float*)d_out;

    cudaFuncSetAttribute(ltc_scan,
                         cudaFuncAttributeMaxDynamicSharedMemorySize,
                         SMEM_SCAN);

    dim3 gemm_grid(M_ / 128, 2);

    // level 0
    xp_gemm<<<gemm_grid, 256>>>(emb, E_, tokens, W_in0, b0);
    ltc_scan<<<B_, 256, SMEM_SCAN>>>(W_rec0, mask0, tau0, out, 0);

    // level 1
    xp_gemm<<<gemm_grid, 256>>>(out, 512, nullptr, W_in1, b1);
    ltc_scan<<<B_, 256, SMEM_SCAN>>>(W_rec1, mask1, tau1, out, 256);
}